// round 5
// baseline (speedup 1.0000x reference)
#include <cuda_runtime.h>

#define N_PARTICLES_MAX 262144

__device__ float4 g_x4[N_PARTICLES_MAX];
__device__ double g_sum;
__device__ unsigned int g_count;

// Repack x [N,3] -> float4 (16B-aligned), zero accumulator + ticket counter.
// Each thread handles 4 particles: 3x float4 loads, 4x float4 stores.
__global__ void repack_kernel(const float4* __restrict__ x4, int n_quads) {
    int t = blockIdx.x * blockDim.x + threadIdx.x;
    if (t == 0) { g_sum = 0.0; g_count = 0u; }
    if (t < n_quads) {
        float4 a = x4[3 * t + 0];   // p0.x p0.y p0.z p1.x
        float4 b = x4[3 * t + 1];   // p1.y p1.z p2.x p2.y
        float4 c = x4[3 * t + 2];   // p2.z p3.x p3.y p3.z
        int p = 4 * t;
        g_x4[p + 0] = make_float4(a.x, a.y, a.z, 0.0f);
        g_x4[p + 1] = make_float4(a.w, b.x, b.y, 0.0f);
        g_x4[p + 2] = make_float4(b.z, b.w, c.x, 0.0f);
        g_x4[p + 3] = make_float4(c.y, c.z, c.w, 0.0f);
    }
}

// Each thread processes 4 pairs (one int4 from each index stream).
// Last block writes the final result (fused finalize).
__global__ void __launch_bounds__(256) lj_kernel(
        const int4* __restrict__ idx_i4,
        const int4* __restrict__ idx_j4,
        const float* __restrict__ eps_p,
        const float* __restrict__ sigma_p,
        const float* __restrict__ box_p,
        int n4,
        float* __restrict__ out) {
    const float L = box_p[0];
    const float invL = __fdividef(1.0f, L);
    const float sigma = sigma_p[0];
    const float sigma2 = sigma * sigma;

    float acc = 0.0f;

    int t = blockIdx.x * blockDim.x + threadIdx.x;
    int stride = gridDim.x * blockDim.x;
    for (int v = t; v < n4; v += stride) {
        int4 iv = __ldcs(&idx_i4[v]);
        int4 jv = __ldcs(&idx_j4[v]);
        int is[4] = {iv.x, iv.y, iv.z, iv.w};
        int js[4] = {jv.x, jv.y, jv.z, jv.w};
#pragma unroll
        for (int k = 0; k < 4; k++) {
            float4 pi = __ldg(&g_x4[is[k]]);
            float4 pj = __ldg(&g_x4[js[k]]);
            float dx = pi.x - pj.x;
            float dy = pi.y - pj.y;
            float dz = pi.z - pj.z;
            dx -= L * rintf(dx * invL);
            dy -= L * rintf(dy * invL);
            dz -= L * rintf(dz * invL);
            float r2 = fmaf(dx, dx, fmaf(dy, dy, dz * dz));
            float s2 = sigma2 * __fdividef(1.0f, r2);
            float s6 = s2 * s2 * s2;
            acc += fmaf(s6, s6, -s6);   // s12 - s6
        }
    }

    acc *= 4.0f * eps_p[0];

    // warp reduce (float), then block reduce in double, one atomic per block
    for (int off = 16; off > 0; off >>= 1)
        acc += __shfl_down_sync(0xFFFFFFFFu, acc, off);

    __shared__ double warp_sums[8];
    int lane = threadIdx.x & 31;
    int wid  = threadIdx.x >> 5;
    if (lane == 0) warp_sums[wid] = (double)acc;
    __syncthreads();

    if (wid == 0) {
        double s = (lane < 8) ? warp_sums[lane] : 0.0;
        for (int off = 4; off > 0; off >>= 1)
            s += __shfl_down_sync(0xFFFFFFFFu, s, off);
        if (lane == 0) {
            atomicAdd(&g_sum, s);
            __threadfence();
            unsigned int ticket = atomicAdd(&g_count, 1u);
            if (ticket == gridDim.x - 1) {
                out[0] = (float)g_sum;
            }
        }
    }
}

extern "C" void kernel_launch(void* const* d_in, const int* in_sizes, int n_in,
                              void* d_out, int out_size) {
    const float* x       = (const float*)d_in[0];   // [N,3]
    const float* eps_p   = (const float*)d_in[1];   // scalar
    const float* sigma_p = (const float*)d_in[2];   // scalar
    const float* box_p   = (const float*)d_in[3];   // [3]
    const int*   idx_i   = (const int*)d_in[4];     // [n_pairs]
    const int*   idx_j   = (const int*)d_in[5];     // [n_pairs]

    int n_particles = in_sizes[0] / 3;
    int n_pairs     = in_sizes[4];
    int n4          = n_pairs / 4;       // 2M vectors of 4 pairs
    int n_quads     = n_particles / 4;   // 65536

    // 1) repack + zero accumulators
    {
        int threads = 256;
        int blocks = (n_quads + threads - 1) / threads;
        repack_kernel<<<blocks, threads>>>((const float4*)x, n_quads);
    }

    // 2) main pair kernel (fused finalize)
    {
        int threads = 256;
        int blocks = (n4 + threads - 1) / threads;
        if (blocks > 16384) blocks = 16384;  // grid-stride covers the rest
        lj_kernel<<<blocks, threads>>>((const int4*)idx_i, (const int4*)idx_j,
                                       eps_p, sigma_p, box_p, n4,
                                       (float*)d_out);
    }
}

// round 7
// speedup vs baseline: 1.0459x; 1.0459x over previous
#include <cuda_runtime.h>

#define N_PARTICLES_MAX 262144

__device__ float4 g_x4[N_PARTICLES_MAX];
__device__ double g_sum;
__device__ unsigned int g_count;

// Repack x [N,3] -> float4 (16B-aligned), zero accumulator + ticket counter.
// Each thread handles 4 particles: 3x float4 loads, 4x float4 stores.
__global__ void repack_kernel(const float4* __restrict__ x4, int n_quads) {
    int t = blockIdx.x * blockDim.x + threadIdx.x;
    if (t == 0) { g_sum = 0.0; g_count = 0u; }
    if (t < n_quads) {
        float4 a = x4[3 * t + 0];   // p0.x p0.y p0.z p1.x
        float4 b = x4[3 * t + 1];   // p1.y p1.z p2.x p2.y
        float4 c = x4[3 * t + 2];   // p2.z p3.x p3.y p3.z
        int p = 4 * t;
        g_x4[p + 0] = make_float4(a.x, a.y, a.z, 0.0f);
        g_x4[p + 1] = make_float4(a.w, b.x, b.y, 0.0f);
        g_x4[p + 2] = make_float4(b.z, b.w, c.x, 0.0f);
        g_x4[p + 3] = make_float4(c.y, c.z, c.w, 0.0f);
    }
}

// Each thread processes 4 pairs (one int4 from each index stream).
// Inner loop is the round-0 version (fastest measured). Last block writes out.
__global__ void lj_kernel(const int4* __restrict__ idx_i4,
                          const int4* __restrict__ idx_j4,
                          const float* __restrict__ eps_p,
                          const float* __restrict__ sigma_p,
                          const float* __restrict__ box_p,
                          int n4,
                          float* __restrict__ out) {
    const float L = box_p[0];
    const float invL = 1.0f / L;
    const float sigma = sigma_p[0];
    const float sigma2 = sigma * sigma;

    float acc = 0.0f;

    int t = blockIdx.x * blockDim.x + threadIdx.x;
    int stride = gridDim.x * blockDim.x;
    for (int v = t; v < n4; v += stride) {
        int4 iv = idx_i4[v];
        int4 jv = idx_j4[v];
        int is[4] = {iv.x, iv.y, iv.z, iv.w};
        int js[4] = {jv.x, jv.y, jv.z, jv.w};
#pragma unroll
        for (int k = 0; k < 4; k++) {
            float4 pi = __ldg(&g_x4[is[k]]);
            float4 pj = __ldg(&g_x4[js[k]]);
            float dx = pi.x - pj.x;
            float dy = pi.y - pj.y;
            float dz = pi.z - pj.z;
            dx -= L * rintf(dx * invL);
            dy -= L * rintf(dy * invL);
            dz -= L * rintf(dz * invL);
            float r2 = fmaf(dx, dx, fmaf(dy, dy, dz * dz));
            float s2 = sigma2 / r2;
            float s6 = s2 * s2 * s2;
            acc += fmaf(s6, s6, -s6);   // s12 - s6
        }
    }

    acc *= 4.0f * eps_p[0];

    // warp reduce (float), then block reduce in double, one atomic per block
    for (int off = 16; off > 0; off >>= 1)
        acc += __shfl_down_sync(0xFFFFFFFFu, acc, off);

    __shared__ double warp_sums[8];
    int lane = threadIdx.x & 31;
    int wid  = threadIdx.x >> 5;
    if (lane == 0) warp_sums[wid] = (double)acc;
    __syncthreads();

    if (wid == 0) {
        double s = (lane < 8) ? warp_sums[lane] : 0.0;
        for (int off = 4; off > 0; off >>= 1)
            s += __shfl_down_sync(0xFFFFFFFFu, s, off);
        if (lane == 0) {
            atomicAdd(&g_sum, s);
            __threadfence();
            unsigned int ticket = atomicAdd(&g_count, 1u);
            if (ticket == gridDim.x - 1) {
                out[0] = (float)g_sum;
            }
        }
    }
}

extern "C" void kernel_launch(void* const* d_in, const int* in_sizes, int n_in,
                              void* d_out, int out_size) {
    const float* x       = (const float*)d_in[0];   // [N,3]
    const float* eps_p   = (const float*)d_in[1];   // scalar
    const float* sigma_p = (const float*)d_in[2];   // scalar
    const float* box_p   = (const float*)d_in[3];   // [3]
    const int*   idx_i   = (const int*)d_in[4];     // [n_pairs]
    const int*   idx_j   = (const int*)d_in[5];     // [n_pairs]

    int n_particles = in_sizes[0] / 3;
    int n_pairs     = in_sizes[4];
    int n4          = n_pairs / 4;       // 2M vectors of 4 pairs
    int n_quads     = n_particles / 4;   // 65536

    // 1) repack + zero accumulators
    {
        int threads = 256;
        int blocks = (n_quads + threads - 1) / threads;
        repack_kernel<<<blocks, threads>>>((const float4*)x, n_quads);
    }

    // 2) main pair kernel (fused finalize)
    {
        int threads = 256;
        int blocks = (n4 + threads - 1) / threads;
        lj_kernel<<<blocks, threads>>>((const int4*)idx_i, (const int4*)idx_j,
                                       eps_p, sigma_p, box_p, n4,
                                       (float*)d_out);
    }
}